// round 13
// baseline (speedup 1.0000x reference)
#include <cuda_runtime.h>
#include <stdint.h>

// ---------------------------------------------------------------------------
// JAX threefry2x32 (partitionable, verified R1). Lazy thermal noise (R3).
// R13: port REBALANCE. LDC floor = 8 cyc/SMSP vs LDS floor ~2 -> optimal
// const:smem split is ~1:4, not R12's 1:1. A: 2 const + 6 smem j4/k.
// B: 1 const + rest smem per layer. FMA2 pipe becomes the single ceiling.
// Accumulator mapping and k-order unchanged -> bit-identical rel_err.
// ---------------------------------------------------------------------------
#define TB 128
#define ROWS_TOTAL 262144

struct Keys { unsigned int k[16]; };   // ks[i] = (k[2i], k[2i+1])

__device__ float g_nw[3328];           // noisy weights (k-major), staging
__device__ float g_tanh[257];          // tanh LUT on the 1/128 grid
__device__ uint4 g_h1[ROWS_TOTAL * 2]; // packed h1: 32B per row (8 MB)

// Const-bank copy of g_nw as 16B vectors (832 entries).
// L1: [0..512) k*8+j4; L2: [512..704) k*6+j4; L3: [704..800) k*4+j4;
// L4: [800..832) k*2+j4.  (Kernels read only the low j4's from here.)
__constant__ ulonglong2 c_w[832];

__host__ __device__ __forceinline__ void tf2x32(uint32_t k0, uint32_t k1,
                                                uint32_t x0, uint32_t x1,
                                                uint32_t* o0, uint32_t* o1) {
  uint32_t ks2 = k0 ^ k1 ^ 0x1BD11BDAu;
#define TFR(a,b,r) { a += b; b = ((b << (r)) | (b >> (32 - (r)))); b ^= a; }
  x0 += k0; x1 += k1;
  TFR(x0,x1,13) TFR(x0,x1,15) TFR(x0,x1,26) TFR(x0,x1,6)
  x0 += k1;  x1 += ks2 + 1u;
  TFR(x0,x1,17) TFR(x0,x1,29) TFR(x0,x1,16) TFR(x0,x1,24)
  x0 += ks2; x1 += k0 + 2u;
  TFR(x0,x1,13) TFR(x0,x1,15) TFR(x0,x1,26) TFR(x0,x1,6)
  x0 += k0;  x1 += k1 + 3u;
  TFR(x0,x1,17) TFR(x0,x1,29) TFR(x0,x1,16) TFR(x0,x1,24)
  x0 += k1;  x1 += ks2 + 4u;
  TFR(x0,x1,13) TFR(x0,x1,15) TFR(x0,x1,26) TFR(x0,x1,6)
  x0 += ks2; x1 += k0 + 5u;
#undef TFR
  *o0 = x0; *o1 = x1;
}

// --- exact path (weight noise; ulps here shift every row) -------------------
__device__ __forceinline__ float erfinv_xla(float x) {
  float xx = __fmul_rn(x, x);
  float w  = -log1pf(-xx);
  float p;
  if (w < 5.0f) {
    w = __fadd_rn(w, -2.5f);
    p = 2.81022636e-08f;
    p = __fadd_rn(3.43273939e-07f,  __fmul_rn(p, w));
    p = __fadd_rn(-3.5233877e-06f,  __fmul_rn(p, w));
    p = __fadd_rn(-4.39150654e-06f, __fmul_rn(p, w));
    p = __fadd_rn(0.00021858087f,   __fmul_rn(p, w));
    p = __fadd_rn(-0.00125372503f,  __fmul_rn(p, w));
    p = __fadd_rn(-0.00417768164f,  __fmul_rn(p, w));
    p = __fadd_rn(0.246640727f,     __fmul_rn(p, w));
    p = __fadd_rn(1.50140941f,      __fmul_rn(p, w));
  } else {
    w = __fadd_rn(sqrtf(w), -3.0f);
    p = -0.000200214257f;
    p = __fadd_rn(0.000100950558f,  __fmul_rn(p, w));
    p = __fadd_rn(0.00134934322f,   __fmul_rn(p, w));
    p = __fadd_rn(-0.00367342844f,  __fmul_rn(p, w));
    p = __fadd_rn(0.00573950773f,   __fmul_rn(p, w));
    p = __fadd_rn(-0.0076224613f,   __fmul_rn(p, w));
    p = __fadd_rn(0.00943887047f,   __fmul_rn(p, w));
    p = __fadd_rn(1.00167406f,      __fmul_rn(p, w));
    p = __fadd_rn(2.83297682f,      __fmul_rn(p, w));
  }
  return __fmul_rn(p, x);
}

__device__ __forceinline__ float jax_normal_exact(uint32_t k0, uint32_t k1,
                                                  uint32_t idx) {
  uint32_t b0, b1;
  tf2x32(k0, k1, 0u, idx, &b0, &b1);
  uint32_t bits = b0 ^ b1;
  float f = __uint_as_float((bits >> 9) | 0x3f800000u);
  f = __fadd_rn(f, -1.0f);
  const float lo = -0x1.fffffep-1f;
  float u = __fadd_rn(__fmul_rn(f, 2.0f), lo);
  u = fmaxf(u, lo);
  return __fmul_rn(0x1.6a09e6p+0f, erfinv_xla(u));
}

// --- fast thermal path (rare): exact bits, ~1e-3 erfinv, sigma*sqrt2 folded -
#define SC(a) ((float)((a) * 1.1313708498984761e-06))

__device__ __noinline__ float add_thermal(uint32_t k0, uint32_t k1,
                                          uint32_t idx, float acc) {
  uint32_t b0, b1;
  tf2x32(k0, k1, 0u, idx, &b0, &b1);
  uint32_t bits = b0 ^ b1;
  float f = __uint_as_float((bits >> 9) | 0x3f800000u) - 1.0f;
  float u = fmaf(f, 2.0f, -0x1.fffffep-1f);
  float t = fmaf(u, -u, 1.0f);
  float w = fminf(-__logf(t), 5.0f);
  w = w - 2.5f;
  float p = SC(2.81022636e-08);
  p = fmaf(p, w, SC(3.43273939e-07));
  p = fmaf(p, w, SC(-3.5233877e-06));
  p = fmaf(p, w, SC(-4.39150654e-06));
  p = fmaf(p, w, SC(0.00021858087));
  p = fmaf(p, w, SC(-0.00125372503));
  p = fmaf(p, w, SC(-0.00417768164));
  p = fmaf(p, w, SC(0.246640727));
  p = fmaf(p, w, SC(1.50140941));
  return fmaf(p, u, acc);
}

__device__ __forceinline__ float quant_r(uint32_t kt0, uint32_t kt1,
                                         uint32_t idx, float acc) {
  float y = __fmul_rn(acc, 128.0f);
  float r = rintf(y);
  bool need = fabsf(__fadd_rn(y, -r)) >= 0.4985f;
  if (__builtin_expect((int)__ballot_sync(0xffffffffu, need), 0)) {
    float o = add_thermal(kt0, kt1, idx, acc);
    r = rintf(__fmul_rn(o, 128.0f));
  }
  return r;
}

// --- packed f32x2 helpers (sm_10x) ------------------------------------------
__device__ __forceinline__ unsigned long long pack2(float a, float b) {
  unsigned long long r;
  asm("mov.b64 %0, {%1, %2};" : "=l"(r) : "f"(a), "f"(b));
  return r;
}
__device__ __forceinline__ void unpack2(unsigned long long v, float& a, float& b) {
  asm("mov.b64 {%0, %1}, %2;" : "=f"(a), "=f"(b) : "l"(v));
}
__device__ __forceinline__ void fma2(unsigned long long& d,
                                     unsigned long long a, unsigned long long b) {
  asm("fma.rn.f32x2 %0, %1, %2, %0;" : "+l"(d) : "l"(a), "l"(b));
}
__device__ __forceinline__ unsigned long long mul2(unsigned long long a,
                                                   unsigned long long b) {
  unsigned long long r;
  asm("mul.rn.f32x2 %0, %1, %2;" : "=l"(r) : "l"(a), "l"(b));
  return r;
}
#define C99P 0x3F7D70A43F7D70A4ull  // (0.99f, 0.99f)
#define C99_128 (0.99f / 128.0f)    // exactly fl(0.99f)*2^-7

// ---------------------------------------------------------------------------
__global__ void setup_weights(const float* __restrict__ w1,
                              const float* __restrict__ w2,
                              const float* __restrict__ w3,
                              const float* __restrict__ w4, Keys K) {
  int e = blockIdx.x * blockDim.x + threadIdx.x;
  if (e >= 3328) {
    int te = e - 3328;
    if (te < 257) g_tanh[te] = tanhf((te - 128) * 0.0078125f);
    return;
  }
  int layer, off, ID, OD, li;
  const float* w;
  if (e < 2048)      { layer = 0; off = 0;    ID = 64; OD = 32; li = e;        w = w1; }
  else if (e < 2816) { layer = 1; off = 2048; ID = 32; OD = 24; li = e - 2048; w = w2; }
  else if (e < 3200) { layer = 2; off = 2816; ID = 24; OD = 16; li = e - 2816; w = w3; }
  else               { layer = 3; off = 3200; ID = 16; OD = 8;  li = e - 3200; w = w4; }
  int j = li / ID, kk = li % ID;
  float z = jax_normal_exact(K.k[4 * layer + 0], K.k[4 * layer + 1], (uint32_t)li);
  float g = expf(__fmul_rn(z, 0.12f));
  g_nw[off + kk * OD + j] = __fmul_rn(w[li], g);
}

// ---------------------------------------------------------------------------
// Epilogue for one accumulator pair: quantize+relu-clip, pack 2 bytes.
__device__ __forceinline__ uint32_t quant_pack2(uint32_t kt0, uint32_t kt1,
                                                uint32_t idx, unsigned long long acc) {
  float a, b;
  unpack2(acc, a, b);
  float r0 = quant_r(kt0, kt1, idx,     a);
  float r1 = quant_r(kt0, kt1, idx + 1, b);
  uint32_t n0 = (uint32_t)__float2int_rn(fminf(fmaxf(r0, 0.0f), 128.0f));
  uint32_t n1 = (uint32_t)__float2int_rn(fminf(fmaxf(r1, 0.0f), 128.0f));
  return n0 | (n1 << 8);
}

// ===========================================================================
// KERNEL A: layer 1. Weights: j4 0..1 via const port, j4 2..7 via smem port.
// ===========================================================================
__global__ void __launch_bounds__(TB, 7)
actor_l1(const float* __restrict__ x, Keys K) {
  __shared__ ulonglong2 s_w[384];      // [k][j4-2], 6 KB
  int tid = threadIdx.x;
  {
    const ulonglong2* gw2 = (const ulonglong2*)g_nw;
#pragma unroll
    for (int i = 0; i < 3; i++) {
      int idx = tid + i * TB;
      int k = idx / 6, jh = idx % 6;
      s_w[idx] = gw2[k * 8 + 2 + jh];
    }
  }
  __syncthreads();

  uint32_t row = blockIdx.x * TB + tid;

  unsigned long long acc[16];
#pragma unroll
  for (int j = 0; j < 16; j++) acc[j] = 0ull;
  const float4* xr = (const float4*)(x + (size_t)row * 64);
#pragma unroll 4
  for (int k4 = 0; k4 < 16; k4++) {
    float4 xv = __ldg(xr + k4);
    float xk[4] = {xv.x, xv.y, xv.z, xv.w};
#pragma unroll
    for (int c = 0; c < 4; c++) {
      int k = 4 * k4 + c;
      unsigned long long xp = mul2(pack2(xk[c], xk[c]), C99P);
#pragma unroll
      for (int j = 0; j < 2; j++) {         // const port: outputs 0..7
        ulonglong2 wv = c_w[k * 8 + j];
        fma2(acc[2 * j],     xp, wv.x);
        fma2(acc[2 * j + 1], xp, wv.y);
      }
#pragma unroll
      for (int j = 0; j < 6; j++) {         // smem port: outputs 8..31
        ulonglong2 wv = s_w[k * 6 + j];
        fma2(acc[4 + 2 * j], xp, wv.x);
        fma2(acc[5 + 2 * j], xp, wv.y);
      }
    }
  }
  uint32_t base = row * 32u;
  uint32_t h1p[8];
#pragma unroll
  for (int j4 = 0; j4 < 8; j4++) {
    uint32_t w = quant_pack2(K.k[2], K.k[3], base + 4 * j4,     acc[2 * j4]);
    w |= quant_pack2(K.k[2], K.k[3], base + 4 * j4 + 2, acc[2 * j4 + 1]) << 16;
    h1p[j4] = w;
  }
  g_h1[row * 2]     = make_uint4(h1p[0], h1p[1], h1p[2], h1p[3]);
  g_h1[row * 2 + 1] = make_uint4(h1p[4], h1p[5], h1p[6], h1p[7]);
}

// ===========================================================================
// KERNEL B: layers 2-4, byte-packed; 1 const j4 + rest smem per layer.
// ===========================================================================
template <int ID, int OD, int CBASE, int JC>
__device__ __forceinline__ void dense_packed(const uint32_t* __restrict__ hinP,
                                             uint32_t* __restrict__ houtP,
                                             const ulonglong2* __restrict__ sw,
                                             uint32_t kt0, uint32_t kt1,
                                             uint32_t base) {
  constexpr int JH = OD / 4 - JC;      // smem j4's per k
  unsigned long long acc[OD / 2];
#pragma unroll
  for (int j = 0; j < OD / 2; j++) acc[j] = 0ull;
#pragma unroll
  for (int k4 = 0; k4 < ID / 4; k4++) {
    uint32_t pw = hinP[k4];
#pragma unroll
    for (int c = 0; c < 4; c++) {
      int k = 4 * k4 + c;
      uint32_t n = (pw >> (8 * c)) & 0xFFu;
      float xs = __fmul_rn((float)n, C99_128);
      unsigned long long xp = pack2(xs, xs);
#pragma unroll
      for (int j = 0; j < JC; j++) {        // const port
        ulonglong2 wv = c_w[CBASE + k * (OD / 4) + j];
        fma2(acc[2 * j],     xp, wv.x);
        fma2(acc[2 * j + 1], xp, wv.y);
      }
#pragma unroll
      for (int j = 0; j < JH; j++) {        // smem port
        ulonglong2 wv = sw[k * JH + j];
        fma2(acc[2 * (JC + j)],     xp, wv.x);
        fma2(acc[2 * (JC + j) + 1], xp, wv.y);
      }
    }
  }
#pragma unroll
  for (int j4 = 0; j4 < OD / 4; j4++) {
    uint32_t w = quant_pack2(kt0, kt1, base + 4 * j4,     acc[2 * j4]);
    w |= quant_pack2(kt0, kt1, base + 4 * j4 + 2, acc[2 * j4 + 1]) << 16;
    houtP[j4] = w;
  }
}

__global__ void __launch_bounds__(TB, 8)
actor_l234(float* __restrict__ out, Keys K) {
  __shared__ ulonglong2 s_wB[248];     // L2 high @0 (160), L3 high @160 (72), L4 high @232 (16)
  __shared__ float s_tanh[257];
  int tid = threadIdx.x;
  {
    const ulonglong2* gw2 = (const ulonglong2*)g_nw;
#pragma unroll
    for (int i = 0; i < 2; i++) {
      int idx = tid + i * TB;
      if (idx < 248) {
        ulonglong2 v;
        if (idx < 160)      { int k = idx / 5, jh = idx % 5; v = gw2[512 + k * 6 + 1 + jh]; }
        else if (idx < 232) { int i2 = idx - 160; int k = i2 / 3, jh = i2 % 3; v = gw2[704 + k * 4 + 1 + jh]; }
        else                { int k = idx - 232; v = gw2[800 + k * 2 + 1]; }
        s_wB[idx] = v;
      }
    }
    for (int i = tid; i < 257; i += TB) s_tanh[i] = g_tanh[i];
  }
  __syncthreads();

  uint32_t row = blockIdx.x * TB + tid;

  uint32_t h1p[8];
  {
    uint4 a = g_h1[row * 2];
    uint4 b = g_h1[row * 2 + 1];
    h1p[0] = a.x; h1p[1] = a.y; h1p[2] = a.z; h1p[3] = a.w;
    h1p[4] = b.x; h1p[5] = b.y; h1p[6] = b.z; h1p[7] = b.w;
  }

  uint32_t h2p[6], h3p[4];
  dense_packed<32, 24, 512, 1>(h1p, h2p, s_wB,       K.k[6],  K.k[7],  row * 24u);
  dense_packed<24, 16, 704, 1>(h2p, h3p, s_wB + 160, K.k[10], K.k[11], row * 16u);

  // ---- layer 4: j4=0 const, j4=1 smem; no relu, clip, tanh LUT ----
  float o4[8];
  {
    unsigned long long acc[4];
#pragma unroll
    for (int j = 0; j < 4; j++) acc[j] = 0ull;
#pragma unroll
    for (int k4 = 0; k4 < 4; k4++) {
      uint32_t pw = h3p[k4];
#pragma unroll
      for (int c = 0; c < 4; c++) {
        int k = 4 * k4 + c;
        uint32_t n = (pw >> (8 * c)) & 0xFFu;
        float xs = __fmul_rn((float)n, C99_128);
        unsigned long long xp = pack2(xs, xs);
        {
          ulonglong2 wv = c_w[800 + k * 2];
          fma2(acc[0], xp, wv.x);
          fma2(acc[1], xp, wv.y);
        }
        {
          ulonglong2 wv = s_wB[232 + k];
          fma2(acc[2], xp, wv.x);
          fma2(acc[3], xp, wv.y);
        }
      }
    }
    uint32_t base = row * 8u;
#pragma unroll
    for (int j = 0; j < 4; j++) {
      float a, b;
      unpack2(acc[j], a, b);
      float r0 = quant_r(K.k[14], K.k[15], base + 2 * j,     a);
      float r1 = quant_r(K.k[14], K.k[15], base + 2 * j + 1, b);
      r0 = fminf(fmaxf(r0, -128.0f), 128.0f);
      r1 = fminf(fmaxf(r1, -128.0f), 128.0f);
      o4[2 * j]     = s_tanh[__float2int_rn(r0) + 128];
      o4[2 * j + 1] = s_tanh[__float2int_rn(r1) + 128];
    }
  }

  float* op = out + (size_t)row * 8;
  *(float4*)op       = make_float4(o4[0], o4[1], o4[2], o4[3]);
  *(float4*)(op + 4) = make_float4(o4[4], o4[5], o4[6], o4[7]);
}

// ---------------------------------------------------------------------------
extern "C" void kernel_launch(void* const* d_in, const int* in_sizes, int n_in,
                              void* d_out, int out_size) {
  const float* x  = (const float*)d_in[0];
  const float* w1 = (const float*)d_in[1];
  const float* w2 = (const float*)d_in[2];
  const float* w3 = (const float*)d_in[3];
  const float* w4 = (const float*)d_in[4];
  int rows = in_sizes[0] / 64;

  Keys K;
  for (int i = 0; i < 8; i++) {
    uint32_t a, b;
    tf2x32(0u, 42u, 0u, (uint32_t)i, &a, &b);
    K.k[2 * i] = a; K.k[2 * i + 1] = b;
  }

  setup_weights<<<(3328 + 257 + 255) / 256, 256>>>(w1, w2, w3, w4, K);

  // Stage noisy weights into the constant bank (D2D, graph-capturable).
  void* src = nullptr;
  cudaGetSymbolAddress(&src, g_nw);
  cudaMemcpyToSymbolAsync(c_w, src, 3328 * sizeof(float), 0,
                          cudaMemcpyDeviceToDevice, 0);

  actor_l1<<<rows / TB, TB>>>(x, K);
  actor_l234<<<rows / TB, TB>>>((float*)d_out, K);
}

// round 14
// speedup vs baseline: 1.0467x; 1.0467x over previous
#include <cuda_runtime.h>
#include <stdint.h>

// ---------------------------------------------------------------------------
// JAX threefry2x32 (partitionable, verified R1). Lazy thermal noise (R3).
// R14: R12 base (dual-port 1:1 const/smem weight split — measured optimum).
// Changes: (1) const/smem FMAs interleaved per k-step to break LDC->LDC /
// LDS->LDS structural stalls; (2) kernel B processes 2 rows/thread (halves
// its per-row weight-port traffic; small live state, launch_bounds(128,5)).
// Per-accumulator k-chains unchanged -> bit-identical rel_err.
// ---------------------------------------------------------------------------
#define TB 128
#define ROWS_TOTAL 262144

struct Keys { unsigned int k[16]; };   // ks[i] = (k[2i], k[2i+1])

__device__ float g_nw[3328];           // noisy weights (k-major), staging
__device__ float g_tanh[257];          // tanh LUT on the 1/128 grid
__device__ uint4 g_h1[ROWS_TOTAL * 2]; // packed h1: 32B per row (8 MB)

// Const-bank copy of g_nw as 16B vectors (832 entries).
// L1: [0..512) k*8+j4; L2: [512..704) k*6+j4; L3: [704..800) k*4+j4;
// L4: [800..832) k*2+j4.
__constant__ ulonglong2 c_w[832];

__host__ __device__ __forceinline__ void tf2x32(uint32_t k0, uint32_t k1,
                                                uint32_t x0, uint32_t x1,
                                                uint32_t* o0, uint32_t* o1) {
  uint32_t ks2 = k0 ^ k1 ^ 0x1BD11BDAu;
#define TFR(a,b,r) { a += b; b = ((b << (r)) | (b >> (32 - (r)))); b ^= a; }
  x0 += k0; x1 += k1;
  TFR(x0,x1,13) TFR(x0,x1,15) TFR(x0,x1,26) TFR(x0,x1,6)
  x0 += k1;  x1 += ks2 + 1u;
  TFR(x0,x1,17) TFR(x0,x1,29) TFR(x0,x1,16) TFR(x0,x1,24)
  x0 += ks2; x1 += k0 + 2u;
  TFR(x0,x1,13) TFR(x0,x1,15) TFR(x0,x1,26) TFR(x0,x1,6)
  x0 += k0;  x1 += k1 + 3u;
  TFR(x0,x1,17) TFR(x0,x1,29) TFR(x0,x1,16) TFR(x0,x1,24)
  x0 += k1;  x1 += ks2 + 4u;
  TFR(x0,x1,13) TFR(x0,x1,15) TFR(x0,x1,26) TFR(x0,x1,6)
  x0 += ks2; x1 += k0 + 5u;
#undef TFR
  *o0 = x0; *o1 = x1;
}

// --- exact path (weight noise; ulps here shift every row) -------------------
__device__ __forceinline__ float erfinv_xla(float x) {
  float xx = __fmul_rn(x, x);
  float w  = -log1pf(-xx);
  float p;
  if (w < 5.0f) {
    w = __fadd_rn(w, -2.5f);
    p = 2.81022636e-08f;
    p = __fadd_rn(3.43273939e-07f,  __fmul_rn(p, w));
    p = __fadd_rn(-3.5233877e-06f,  __fmul_rn(p, w));
    p = __fadd_rn(-4.39150654e-06f, __fmul_rn(p, w));
    p = __fadd_rn(0.00021858087f,   __fmul_rn(p, w));
    p = __fadd_rn(-0.00125372503f,  __fmul_rn(p, w));
    p = __fadd_rn(-0.00417768164f,  __fmul_rn(p, w));
    p = __fadd_rn(0.246640727f,     __fmul_rn(p, w));
    p = __fadd_rn(1.50140941f,      __fmul_rn(p, w));
  } else {
    w = __fadd_rn(sqrtf(w), -3.0f);
    p = -0.000200214257f;
    p = __fadd_rn(0.000100950558f,  __fmul_rn(p, w));
    p = __fadd_rn(0.00134934322f,   __fmul_rn(p, w));
    p = __fadd_rn(-0.00367342844f,  __fmul_rn(p, w));
    p = __fadd_rn(0.00573950773f,   __fmul_rn(p, w));
    p = __fadd_rn(-0.0076224613f,   __fmul_rn(p, w));
    p = __fadd_rn(0.00943887047f,   __fmul_rn(p, w));
    p = __fadd_rn(1.00167406f,      __fmul_rn(p, w));
    p = __fadd_rn(2.83297682f,      __fmul_rn(p, w));
  }
  return __fmul_rn(p, x);
}

__device__ __forceinline__ float jax_normal_exact(uint32_t k0, uint32_t k1,
                                                  uint32_t idx) {
  uint32_t b0, b1;
  tf2x32(k0, k1, 0u, idx, &b0, &b1);
  uint32_t bits = b0 ^ b1;
  float f = __uint_as_float((bits >> 9) | 0x3f800000u);
  f = __fadd_rn(f, -1.0f);
  const float lo = -0x1.fffffep-1f;
  float u = __fadd_rn(__fmul_rn(f, 2.0f), lo);
  u = fmaxf(u, lo);
  return __fmul_rn(0x1.6a09e6p+0f, erfinv_xla(u));
}

// --- fast thermal path (rare): exact bits, ~1e-3 erfinv, sigma*sqrt2 folded -
#define SC(a) ((float)((a) * 1.1313708498984761e-06))

__device__ __noinline__ float add_thermal(uint32_t k0, uint32_t k1,
                                          uint32_t idx, float acc) {
  uint32_t b0, b1;
  tf2x32(k0, k1, 0u, idx, &b0, &b1);
  uint32_t bits = b0 ^ b1;
  float f = __uint_as_float((bits >> 9) | 0x3f800000u) - 1.0f;
  float u = fmaf(f, 2.0f, -0x1.fffffep-1f);
  float t = fmaf(u, -u, 1.0f);
  float w = fminf(-__logf(t), 5.0f);
  w = w - 2.5f;
  float p = SC(2.81022636e-08);
  p = fmaf(p, w, SC(3.43273939e-07));
  p = fmaf(p, w, SC(-3.5233877e-06));
  p = fmaf(p, w, SC(-4.39150654e-06));
  p = fmaf(p, w, SC(0.00021858087));
  p = fmaf(p, w, SC(-0.00125372503));
  p = fmaf(p, w, SC(-0.00417768164));
  p = fmaf(p, w, SC(0.246640727));
  p = fmaf(p, w, SC(1.50140941));
  return fmaf(p, u, acc);
}

__device__ __forceinline__ float quant_r(uint32_t kt0, uint32_t kt1,
                                         uint32_t idx, float acc) {
  float y = __fmul_rn(acc, 128.0f);
  float r = rintf(y);
  bool need = fabsf(__fadd_rn(y, -r)) >= 0.4985f;
  if (__builtin_expect((int)__ballot_sync(0xffffffffu, need), 0)) {
    float o = add_thermal(kt0, kt1, idx, acc);
    r = rintf(__fmul_rn(o, 128.0f));
  }
  return r;
}

// --- packed f32x2 helpers (sm_10x) ------------------------------------------
__device__ __forceinline__ unsigned long long pack2(float a, float b) {
  unsigned long long r;
  asm("mov.b64 %0, {%1, %2};" : "=l"(r) : "f"(a), "f"(b));
  return r;
}
__device__ __forceinline__ void unpack2(unsigned long long v, float& a, float& b) {
  asm("mov.b64 {%0, %1}, %2;" : "=f"(a), "=f"(b) : "l"(v));
}
__device__ __forceinline__ void fma2(unsigned long long& d,
                                     unsigned long long a, unsigned long long b) {
  asm("fma.rn.f32x2 %0, %1, %2, %0;" : "+l"(d) : "l"(a), "l"(b));
}
__device__ __forceinline__ unsigned long long mul2(unsigned long long a,
                                                   unsigned long long b) {
  unsigned long long r;
  asm("mul.rn.f32x2 %0, %1, %2;" : "=l"(r) : "l"(a), "l"(b));
  return r;
}
#define C99P 0x3F7D70A43F7D70A4ull  // (0.99f, 0.99f)
#define C99_128 (0.99f / 128.0f)    // exactly fl(0.99f)*2^-7

// ---------------------------------------------------------------------------
__global__ void setup_weights(const float* __restrict__ w1,
                              const float* __restrict__ w2,
                              const float* __restrict__ w3,
                              const float* __restrict__ w4, Keys K) {
  int e = blockIdx.x * blockDim.x + threadIdx.x;
  if (e >= 3328) {
    int te = e - 3328;
    if (te < 257) g_tanh[te] = tanhf((te - 128) * 0.0078125f);
    return;
  }
  int layer, off, ID, OD, li;
  const float* w;
  if (e < 2048)      { layer = 0; off = 0;    ID = 64; OD = 32; li = e;        w = w1; }
  else if (e < 2816) { layer = 1; off = 2048; ID = 32; OD = 24; li = e - 2048; w = w2; }
  else if (e < 3200) { layer = 2; off = 2816; ID = 24; OD = 16; li = e - 2816; w = w3; }
  else               { layer = 3; off = 3200; ID = 16; OD = 8;  li = e - 3200; w = w4; }
  int j = li / ID, kk = li % ID;
  float z = jax_normal_exact(K.k[4 * layer + 0], K.k[4 * layer + 1], (uint32_t)li);
  float g = expf(__fmul_rn(z, 0.12f));
  g_nw[off + kk * OD + j] = __fmul_rn(w[li], g);
}

// ---------------------------------------------------------------------------
// Epilogue for one accumulator pair: quantize+relu-clip, pack 2 bytes.
__device__ __forceinline__ uint32_t quant_pack2(uint32_t kt0, uint32_t kt1,
                                                uint32_t idx, unsigned long long acc) {
  float a, b;
  unpack2(acc, a, b);
  float r0 = quant_r(kt0, kt1, idx,     a);
  float r1 = quant_r(kt0, kt1, idx + 1, b);
  uint32_t n0 = (uint32_t)__float2int_rn(fminf(fmaxf(r0, 0.0f), 128.0f));
  uint32_t n1 = (uint32_t)__float2int_rn(fminf(fmaxf(r1, 0.0f), 128.0f));
  return n0 | (n1 << 8);
}

// ===========================================================================
// KERNEL A: layer 1. 1 row/thread. j4 0..3 const, 4..7 smem, interleaved.
// ===========================================================================
__global__ void __launch_bounds__(TB, 7)
actor_l1(const float* __restrict__ x, Keys K) {
  __shared__ ulonglong2 s_w[256];      // [k][j4-4], 4 KB
  int tid = threadIdx.x;
  {
    const ulonglong2* gw2 = (const ulonglong2*)g_nw;
#pragma unroll
    for (int i = 0; i < 2; i++) {
      int idx = tid + i * TB;
      int k = idx >> 2, jh = idx & 3;
      s_w[idx] = gw2[k * 8 + 4 + jh];
    }
  }
  __syncthreads();

  uint32_t row = blockIdx.x * TB + tid;

  unsigned long long acc[16];
#pragma unroll
  for (int j = 0; j < 16; j++) acc[j] = 0ull;
  const float4* xr = (const float4*)(x + (size_t)row * 64);
#pragma unroll 4
  for (int k4 = 0; k4 < 16; k4++) {
    float4 xv = __ldg(xr + k4);
    float xk[4] = {xv.x, xv.y, xv.z, xv.w};
#pragma unroll
    for (int c = 0; c < 4; c++) {
      int k = 4 * k4 + c;
      unsigned long long xp = mul2(pack2(xk[c], xk[c]), C99P);
#pragma unroll
      for (int j = 0; j < 4; j++) {     // interleave const / smem ports
        ulonglong2 wc = c_w[k * 8 + j];
        ulonglong2 ws = s_w[k * 4 + j];
        fma2(acc[2 * j],     xp, wc.x);
        fma2(acc[8 + 2 * j], xp, ws.x);
        fma2(acc[2 * j + 1], xp, wc.y);
        fma2(acc[9 + 2 * j], xp, ws.y);
      }
    }
  }
  uint32_t base = row * 32u;
  uint32_t h1p[8];
#pragma unroll
  for (int j4 = 0; j4 < 8; j4++) {
    uint32_t w = quant_pack2(K.k[2], K.k[3], base + 4 * j4,     acc[2 * j4]);
    w |= quant_pack2(K.k[2], K.k[3], base + 4 * j4 + 2, acc[2 * j4 + 1]) << 16;
    h1p[j4] = w;
  }
  g_h1[row * 2]     = make_uint4(h1p[0], h1p[1], h1p[2], h1p[3]);
  g_h1[row * 2 + 1] = make_uint4(h1p[4], h1p[5], h1p[6], h1p[7]);
}

// ===========================================================================
// KERNEL B: layers 2-4, byte-packed, TWO rows/thread, dual-port interleaved.
// ===========================================================================
template <int ID, int OD, int CBASE, int JC>
__device__ __forceinline__ void dense_packed2(const uint32_t* __restrict__ hpA,
                                              const uint32_t* __restrict__ hpB,
                                              uint32_t* __restrict__ hoA,
                                              uint32_t* __restrict__ hoB,
                                              const ulonglong2* __restrict__ sw,
                                              uint32_t kt0, uint32_t kt1,
                                              uint32_t baseA, uint32_t baseB) {
  constexpr int JH = OD / 4 - JC;      // smem j4's per k
  constexpr int JM = (JC > JH) ? JC : JH;
  unsigned long long accA[OD / 2], accB[OD / 2];
#pragma unroll
  for (int j = 0; j < OD / 2; j++) { accA[j] = 0ull; accB[j] = 0ull; }
#pragma unroll
  for (int k4 = 0; k4 < ID / 4; k4++) {
    uint32_t pwA = hpA[k4], pwB = hpB[k4];
#pragma unroll
    for (int c = 0; c < 4; c++) {
      int k = 4 * k4 + c;
      uint32_t nA = (pwA >> (8 * c)) & 0xFFu;
      uint32_t nB = (pwB >> (8 * c)) & 0xFFu;
      float xsA = __fmul_rn((float)nA, C99_128);
      float xsB = __fmul_rn((float)nB, C99_128);
      unsigned long long xpA = pack2(xsA, xsA);
      unsigned long long xpB = pack2(xsB, xsB);
#pragma unroll
      for (int j = 0; j < JM; j++) {    // interleave const / smem ports
        if (j < JC) {
          ulonglong2 wv = c_w[CBASE + k * (OD / 4) + j];
          fma2(accA[2 * j],     xpA, wv.x);
          fma2(accB[2 * j],     xpB, wv.x);
          fma2(accA[2 * j + 1], xpA, wv.y);
          fma2(accB[2 * j + 1], xpB, wv.y);
        }
        if (j < JH) {
          ulonglong2 wv = sw[k * JH + j];
          fma2(accA[2 * (JC + j)],     xpA, wv.x);
          fma2(accB[2 * (JC + j)],     xpB, wv.x);
          fma2(accA[2 * (JC + j) + 1], xpA, wv.y);
          fma2(accB[2 * (JC + j) + 1], xpB, wv.y);
        }
      }
    }
  }
#pragma unroll
  for (int j4 = 0; j4 < OD / 4; j4++) {
    uint32_t wA = quant_pack2(kt0, kt1, baseA + 4 * j4,     accA[2 * j4]);
    wA |= quant_pack2(kt0, kt1, baseA + 4 * j4 + 2, accA[2 * j4 + 1]) << 16;
    uint32_t wB = quant_pack2(kt0, kt1, baseB + 4 * j4,     accB[2 * j4]);
    wB |= quant_pack2(kt0, kt1, baseB + 4 * j4 + 2, accB[2 * j4 + 1]) << 16;
    hoA[j4] = wA;
    hoB[j4] = wB;
  }
}

__global__ void __launch_bounds__(TB, 5)
actor_l234(float* __restrict__ out, Keys K) {
  __shared__ ulonglong2 s_wB[160];     // L2 high @0 (96), L3 high @96 (48), L4 high @144 (16)
  __shared__ float s_tanh[257];
  int tid = threadIdx.x;
  {
    const ulonglong2* gw2 = (const ulonglong2*)g_nw;
#pragma unroll
    for (int i = 0; i < 2; i++) {
      int idx = tid + i * TB;
      if (idx < 160) {
        ulonglong2 v;
        if (idx < 96)       { int k = idx / 3, jh = idx % 3; v = gw2[512 + k * 6 + 3 + jh]; }
        else if (idx < 144) { int i2 = idx - 96; int k = i2 / 2, jh = i2 % 2; v = gw2[704 + k * 4 + 2 + jh]; }
        else                { int k = idx - 144; v = gw2[800 + k * 2 + 1]; }
        s_wB[idx] = v;
      }
    }
    for (int i = tid; i < 257; i += TB) s_tanh[i] = g_tanh[i];
  }
  __syncthreads();

  uint32_t rowA = blockIdx.x * (2 * TB) + tid;   // coalesced stream A
  uint32_t rowB = rowA + TB;                      // coalesced stream B

  uint32_t h1pA[8], h1pB[8];
  {
    uint4 a0 = g_h1[rowA * 2];
    uint4 a1 = g_h1[rowA * 2 + 1];
    uint4 b0 = g_h1[rowB * 2];
    uint4 b1 = g_h1[rowB * 2 + 1];
    h1pA[0] = a0.x; h1pA[1] = a0.y; h1pA[2] = a0.z; h1pA[3] = a0.w;
    h1pA[4] = a1.x; h1pA[5] = a1.y; h1pA[6] = a1.z; h1pA[7] = a1.w;
    h1pB[0] = b0.x; h1pB[1] = b0.y; h1pB[2] = b0.z; h1pB[3] = b0.w;
    h1pB[4] = b1.x; h1pB[5] = b1.y; h1pB[6] = b1.z; h1pB[7] = b1.w;
  }

  uint32_t h2pA[6], h2pB[6], h3pA[4], h3pB[4];
  dense_packed2<32, 24, 512, 3>(h1pA, h1pB, h2pA, h2pB, s_wB,
                                K.k[6],  K.k[7],  rowA * 24u, rowB * 24u);
  dense_packed2<24, 16, 704, 2>(h2pA, h2pB, h3pA, h3pB, s_wB + 96,
                                K.k[10], K.k[11], rowA * 16u, rowB * 16u);

  // ---- layer 4: j4=0 const, j4=1 smem; no relu, clip, tanh LUT ----
  {
    unsigned long long accA[4], accB[4];
#pragma unroll
    for (int j = 0; j < 4; j++) { accA[j] = 0ull; accB[j] = 0ull; }
#pragma unroll
    for (int k4 = 0; k4 < 4; k4++) {
      uint32_t pwA = h3pA[k4], pwB = h3pB[k4];
#pragma unroll
      for (int c = 0; c < 4; c++) {
        int k = 4 * k4 + c;
        uint32_t nA = (pwA >> (8 * c)) & 0xFFu;
        uint32_t nB = (pwB >> (8 * c)) & 0xFFu;
        float xsA = __fmul_rn((float)nA, C99_128);
        float xsB = __fmul_rn((float)nB, C99_128);
        unsigned long long xpA = pack2(xsA, xsA);
        unsigned long long xpB = pack2(xsB, xsB);
        ulonglong2 wc = c_w[800 + k * 2];
        ulonglong2 ws = s_wB[144 + k];
        fma2(accA[0], xpA, wc.x);
        fma2(accA[2], xpA, ws.x);
        fma2(accB[0], xpB, wc.x);
        fma2(accB[2], xpB, ws.x);
        fma2(accA[1], xpA, wc.y);
        fma2(accA[3], xpA, ws.y);
        fma2(accB[1], xpB, wc.y);
        fma2(accB[3], xpB, ws.y);
      }
    }
    uint32_t baseA = rowA * 8u, baseB = rowB * 8u;
    float o4A[8], o4B[8];
#pragma unroll
    for (int j = 0; j < 4; j++) {
      float a0, a1, b0, b1;
      unpack2(accA[j], a0, a1);
      unpack2(accB[j], b0, b1);
      float rA0 = quant_r(K.k[14], K.k[15], baseA + 2 * j,     a0);
      float rA1 = quant_r(K.k[14], K.k[15], baseA + 2 * j + 1, a1);
      float rB0 = quant_r(K.k[14], K.k[15], baseB + 2 * j,     b0);
      float rB1 = quant_r(K.k[14], K.k[15], baseB + 2 * j + 1, b1);
      rA0 = fminf(fmaxf(rA0, -128.0f), 128.0f);
      rA1 = fminf(fmaxf(rA1, -128.0f), 128.0f);
      rB0 = fminf(fmaxf(rB0, -128.0f), 128.0f);
      rB1 = fminf(fmaxf(rB1, -128.0f), 128.0f);
      o4A[2 * j]     = s_tanh[__float2int_rn(rA0) + 128];
      o4A[2 * j + 1] = s_tanh[__float2int_rn(rA1) + 128];
      o4B[2 * j]     = s_tanh[__float2int_rn(rB0) + 128];
      o4B[2 * j + 1] = s_tanh[__float2int_rn(rB1) + 128];
    }
    float* opA = out + (size_t)rowA * 8;
    float* opB = out + (size_t)rowB * 8;
    *(float4*)opA       = make_float4(o4A[0], o4A[1], o4A[2], o4A[3]);
    *(float4*)(opA + 4) = make_float4(o4A[4], o4A[5], o4A[6], o4A[7]);
    *(float4*)opB       = make_float4(o4B[0], o4B[1], o4B[2], o4B[3]);
    *(float4*)(opB + 4) = make_float4(o4B[4], o4B[5], o4B[6], o4B[7]);
  }
}

// ---------------------------------------------------------------------------
extern "C" void kernel_launch(void* const* d_in, const int* in_sizes, int n_in,
                              void* d_out, int out_size) {
  const float* x  = (const float*)d_in[0];
  const float* w1 = (const float*)d_in[1];
  const float* w2 = (const float*)d_in[2];
  const float* w3 = (const float*)d_in[3];
  const float* w4 = (const float*)d_in[4];
  int rows = in_sizes[0] / 64;

  Keys K;
  for (int i = 0; i < 8; i++) {
    uint32_t a, b;
    tf2x32(0u, 42u, 0u, (uint32_t)i, &a, &b);
    K.k[2 * i] = a; K.k[2 * i + 1] = b;
  }

  setup_weights<<<(3328 + 257 + 255) / 256, 256>>>(w1, w2, w3, w4, K);

  // Stage noisy weights into the constant bank (D2D, graph-capturable).
  void* src = nullptr;
  cudaGetSymbolAddress(&src, g_nw);
  cudaMemcpyToSymbolAsync(c_w, src, 3328 * sizeof(float), 0,
                          cudaMemcpyDeviceToDevice, 0);

  actor_l1<<<rows / TB, TB>>>(x, K);
  actor_l234<<<rows / (2 * TB), TB>>>((float*)d_out, K);
}

// round 15
// speedup vs baseline: 1.0522x; 1.0052x over previous
#include <cuda_runtime.h>
#include <stdint.h>

// ---------------------------------------------------------------------------
// JAX threefry2x32 (partitionable, verified R1). Lazy thermal noise (R3).
// R15: R12 base (dual-port 1:1 const/smem, measured optimum; A unchanged).
// SINGLE change vs R12: kernel B processes 2 rows/thread with GROUPED port
// loops (R14's confound removed). Halves B's per-row LDC/LDS/ALU.
// Per-accumulator k-chains unchanged -> bit-identical rel_err.
// ---------------------------------------------------------------------------
#define TB 128
#define ROWS_TOTAL 262144

struct Keys { unsigned int k[16]; };   // ks[i] = (k[2i], k[2i+1])

__device__ float g_nw[3328];           // noisy weights (k-major), staging
__device__ float g_tanh[257];          // tanh LUT on the 1/128 grid
__device__ uint4 g_h1[ROWS_TOTAL * 2]; // packed h1: 32B per row (8 MB)

// Const-bank copy of g_nw as 16B vectors (832 entries).
// L1: [0..512) k*8+j4; L2: [512..704) k*6+j4; L3: [704..800) k*4+j4;
// L4: [800..832) k*2+j4.
__constant__ ulonglong2 c_w[832];

__host__ __device__ __forceinline__ void tf2x32(uint32_t k0, uint32_t k1,
                                                uint32_t x0, uint32_t x1,
                                                uint32_t* o0, uint32_t* o1) {
  uint32_t ks2 = k0 ^ k1 ^ 0x1BD11BDAu;
#define TFR(a,b,r) { a += b; b = ((b << (r)) | (b >> (32 - (r)))); b ^= a; }
  x0 += k0; x1 += k1;
  TFR(x0,x1,13) TFR(x0,x1,15) TFR(x0,x1,26) TFR(x0,x1,6)
  x0 += k1;  x1 += ks2 + 1u;
  TFR(x0,x1,17) TFR(x0,x1,29) TFR(x0,x1,16) TFR(x0,x1,24)
  x0 += ks2; x1 += k0 + 2u;
  TFR(x0,x1,13) TFR(x0,x1,15) TFR(x0,x1,26) TFR(x0,x1,6)
  x0 += k0;  x1 += k1 + 3u;
  TFR(x0,x1,17) TFR(x0,x1,29) TFR(x0,x1,16) TFR(x0,x1,24)
  x0 += k1;  x1 += ks2 + 4u;
  TFR(x0,x1,13) TFR(x0,x1,15) TFR(x0,x1,26) TFR(x0,x1,6)
  x0 += ks2; x1 += k0 + 5u;
#undef TFR
  *o0 = x0; *o1 = x1;
}

// --- exact path (weight noise; ulps here shift every row) -------------------
__device__ __forceinline__ float erfinv_xla(float x) {
  float xx = __fmul_rn(x, x);
  float w  = -log1pf(-xx);
  float p;
  if (w < 5.0f) {
    w = __fadd_rn(w, -2.5f);
    p = 2.81022636e-08f;
    p = __fadd_rn(3.43273939e-07f,  __fmul_rn(p, w));
    p = __fadd_rn(-3.5233877e-06f,  __fmul_rn(p, w));
    p = __fadd_rn(-4.39150654e-06f, __fmul_rn(p, w));
    p = __fadd_rn(0.00021858087f,   __fmul_rn(p, w));
    p = __fadd_rn(-0.00125372503f,  __fmul_rn(p, w));
    p = __fadd_rn(-0.00417768164f,  __fmul_rn(p, w));
    p = __fadd_rn(0.246640727f,     __fmul_rn(p, w));
    p = __fadd_rn(1.50140941f,      __fmul_rn(p, w));
  } else {
    w = __fadd_rn(sqrtf(w), -3.0f);
    p = -0.000200214257f;
    p = __fadd_rn(0.000100950558f,  __fmul_rn(p, w));
    p = __fadd_rn(0.00134934322f,   __fmul_rn(p, w));
    p = __fadd_rn(-0.00367342844f,  __fmul_rn(p, w));
    p = __fadd_rn(0.00573950773f,   __fmul_rn(p, w));
    p = __fadd_rn(-0.0076224613f,   __fmul_rn(p, w));
    p = __fadd_rn(0.00943887047f,   __fmul_rn(p, w));
    p = __fadd_rn(1.00167406f,      __fmul_rn(p, w));
    p = __fadd_rn(2.83297682f,      __fmul_rn(p, w));
  }
  return __fmul_rn(p, x);
}

__device__ __forceinline__ float jax_normal_exact(uint32_t k0, uint32_t k1,
                                                  uint32_t idx) {
  uint32_t b0, b1;
  tf2x32(k0, k1, 0u, idx, &b0, &b1);
  uint32_t bits = b0 ^ b1;
  float f = __uint_as_float((bits >> 9) | 0x3f800000u);
  f = __fadd_rn(f, -1.0f);
  const float lo = -0x1.fffffep-1f;
  float u = __fadd_rn(__fmul_rn(f, 2.0f), lo);
  u = fmaxf(u, lo);
  return __fmul_rn(0x1.6a09e6p+0f, erfinv_xla(u));
}

// --- fast thermal path (rare): exact bits, ~1e-3 erfinv, sigma*sqrt2 folded -
#define SC(a) ((float)((a) * 1.1313708498984761e-06))

__device__ __noinline__ float add_thermal(uint32_t k0, uint32_t k1,
                                          uint32_t idx, float acc) {
  uint32_t b0, b1;
  tf2x32(k0, k1, 0u, idx, &b0, &b1);
  uint32_t bits = b0 ^ b1;
  float f = __uint_as_float((bits >> 9) | 0x3f800000u) - 1.0f;
  float u = fmaf(f, 2.0f, -0x1.fffffep-1f);
  float t = fmaf(u, -u, 1.0f);
  float w = fminf(-__logf(t), 5.0f);
  w = w - 2.5f;
  float p = SC(2.81022636e-08);
  p = fmaf(p, w, SC(3.43273939e-07));
  p = fmaf(p, w, SC(-3.5233877e-06));
  p = fmaf(p, w, SC(-4.39150654e-06));
  p = fmaf(p, w, SC(0.00021858087));
  p = fmaf(p, w, SC(-0.00125372503));
  p = fmaf(p, w, SC(-0.00417768164));
  p = fmaf(p, w, SC(0.246640727));
  p = fmaf(p, w, SC(1.50140941));
  return fmaf(p, u, acc);
}

__device__ __forceinline__ float quant_r(uint32_t kt0, uint32_t kt1,
                                         uint32_t idx, float acc) {
  float y = __fmul_rn(acc, 128.0f);
  float r = rintf(y);
  bool need = fabsf(__fadd_rn(y, -r)) >= 0.4985f;
  if (__builtin_expect((int)__ballot_sync(0xffffffffu, need), 0)) {
    float o = add_thermal(kt0, kt1, idx, acc);
    r = rintf(__fmul_rn(o, 128.0f));
  }
  return r;
}

// --- packed f32x2 helpers (sm_10x) ------------------------------------------
__device__ __forceinline__ unsigned long long pack2(float a, float b) {
  unsigned long long r;
  asm("mov.b64 %0, {%1, %2};" : "=l"(r) : "f"(a), "f"(b));
  return r;
}
__device__ __forceinline__ void unpack2(unsigned long long v, float& a, float& b) {
  asm("mov.b64 {%0, %1}, %2;" : "=f"(a), "=f"(b) : "l"(v));
}
__device__ __forceinline__ void fma2(unsigned long long& d,
                                     unsigned long long a, unsigned long long b) {
  asm("fma.rn.f32x2 %0, %1, %2, %0;" : "+l"(d) : "l"(a), "l"(b));
}
__device__ __forceinline__ unsigned long long mul2(unsigned long long a,
                                                   unsigned long long b) {
  unsigned long long r;
  asm("mul.rn.f32x2 %0, %1, %2;" : "=l"(r) : "l"(a), "l"(b));
  return r;
}
#define C99P 0x3F7D70A43F7D70A4ull  // (0.99f, 0.99f)
#define C99_128 (0.99f / 128.0f)    // exactly fl(0.99f)*2^-7

// ---------------------------------------------------------------------------
__global__ void setup_weights(const float* __restrict__ w1,
                              const float* __restrict__ w2,
                              const float* __restrict__ w3,
                              const float* __restrict__ w4, Keys K) {
  int e = blockIdx.x * blockDim.x + threadIdx.x;
  if (e >= 3328) {
    int te = e - 3328;
    if (te < 257) g_tanh[te] = tanhf((te - 128) * 0.0078125f);
    return;
  }
  int layer, off, ID, OD, li;
  const float* w;
  if (e < 2048)      { layer = 0; off = 0;    ID = 64; OD = 32; li = e;        w = w1; }
  else if (e < 2816) { layer = 1; off = 2048; ID = 32; OD = 24; li = e - 2048; w = w2; }
  else if (e < 3200) { layer = 2; off = 2816; ID = 24; OD = 16; li = e - 2816; w = w3; }
  else               { layer = 3; off = 3200; ID = 16; OD = 8;  li = e - 3200; w = w4; }
  int j = li / ID, kk = li % ID;
  float z = jax_normal_exact(K.k[4 * layer + 0], K.k[4 * layer + 1], (uint32_t)li);
  float g = expf(__fmul_rn(z, 0.12f));
  g_nw[off + kk * OD + j] = __fmul_rn(w[li], g);
}

// ---------------------------------------------------------------------------
// Epilogue for one accumulator pair: quantize+relu-clip, pack 2 bytes.
__device__ __forceinline__ uint32_t quant_pack2(uint32_t kt0, uint32_t kt1,
                                                uint32_t idx, unsigned long long acc) {
  float a, b;
  unpack2(acc, a, b);
  float r0 = quant_r(kt0, kt1, idx,     a);
  float r1 = quant_r(kt0, kt1, idx + 1, b);
  uint32_t n0 = (uint32_t)__float2int_rn(fminf(fmaxf(r0, 0.0f), 128.0f));
  uint32_t n1 = (uint32_t)__float2int_rn(fminf(fmaxf(r1, 0.0f), 128.0f));
  return n0 | (n1 << 8);
}

// ===========================================================================
// KERNEL A: layer 1 (EXACTLY R12). j4 0..3 const, 4..7 smem, grouped.
// ===========================================================================
__global__ void __launch_bounds__(TB, 7)
actor_l1(const float* __restrict__ x, Keys K) {
  __shared__ ulonglong2 s_w[256];      // [k][j4-4], 4 KB
  int tid = threadIdx.x;
  {
    const ulonglong2* gw2 = (const ulonglong2*)g_nw;
#pragma unroll
    for (int i = 0; i < 2; i++) {
      int idx = tid + i * TB;
      int k = idx >> 2, jh = idx & 3;
      s_w[idx] = gw2[k * 8 + 4 + jh];
    }
  }
  __syncthreads();

  uint32_t row = blockIdx.x * TB + tid;

  unsigned long long acc[16];
#pragma unroll
  for (int j = 0; j < 16; j++) acc[j] = 0ull;
  const float4* xr = (const float4*)(x + (size_t)row * 64);
#pragma unroll 4
  for (int k4 = 0; k4 < 16; k4++) {
    float4 xv = __ldg(xr + k4);
    float xk[4] = {xv.x, xv.y, xv.z, xv.w};
#pragma unroll
    for (int c = 0; c < 4; c++) {
      int k = 4 * k4 + c;
      unsigned long long xp = mul2(pack2(xk[c], xk[c]), C99P);
#pragma unroll
      for (int j = 0; j < 4; j++) {         // const port: outputs 0..15
        ulonglong2 wv = c_w[k * 8 + j];
        fma2(acc[2 * j],     xp, wv.x);
        fma2(acc[2 * j + 1], xp, wv.y);
      }
#pragma unroll
      for (int j = 0; j < 4; j++) {         // smem port: outputs 16..31
        ulonglong2 wv = s_w[k * 4 + j];
        fma2(acc[8 + 2 * j], xp, wv.x);
        fma2(acc[9 + 2 * j], xp, wv.y);
      }
    }
  }
  uint32_t base = row * 32u;
  uint32_t h1p[8];
#pragma unroll
  for (int j4 = 0; j4 < 8; j4++) {
    uint32_t w = quant_pack2(K.k[2], K.k[3], base + 4 * j4,     acc[2 * j4]);
    w |= quant_pack2(K.k[2], K.k[3], base + 4 * j4 + 2, acc[2 * j4 + 1]) << 16;
    h1p[j4] = w;
  }
  g_h1[row * 2]     = make_uint4(h1p[0], h1p[1], h1p[2], h1p[3]);
  g_h1[row * 2 + 1] = make_uint4(h1p[4], h1p[5], h1p[6], h1p[7]);
}

// ===========================================================================
// KERNEL B: layers 2-4, byte-packed, TWO rows/thread, GROUPED dual-port.
// ===========================================================================
template <int ID, int OD, int CBASE, int JC>
__device__ __forceinline__ void dense_packed2(const uint32_t* __restrict__ hpA,
                                              const uint32_t* __restrict__ hpB,
                                              uint32_t* __restrict__ hoA,
                                              uint32_t* __restrict__ hoB,
                                              const ulonglong2* __restrict__ sw,
                                              uint32_t kt0, uint32_t kt1,
                                              uint32_t baseA, uint32_t baseB) {
  constexpr int JH = OD / 4 - JC;      // smem j4's per k
  unsigned long long accA[OD / 2], accB[OD / 2];
#pragma unroll
  for (int j = 0; j < OD / 2; j++) { accA[j] = 0ull; accB[j] = 0ull; }
#pragma unroll
  for (int k4 = 0; k4 < ID / 4; k4++) {
    uint32_t pwA = hpA[k4], pwB = hpB[k4];
#pragma unroll
    for (int c = 0; c < 4; c++) {
      int k = 4 * k4 + c;
      uint32_t nA = (pwA >> (8 * c)) & 0xFFu;
      uint32_t nB = (pwB >> (8 * c)) & 0xFFu;
      float xsA = __fmul_rn((float)nA, C99_128);
      float xsB = __fmul_rn((float)nB, C99_128);
      unsigned long long xpA = pack2(xsA, xsA);
      unsigned long long xpB = pack2(xsB, xsB);
#pragma unroll
      for (int j = 0; j < JC; j++) {        // const port (shared by both rows)
        ulonglong2 wv = c_w[CBASE + k * (OD / 4) + j];
        fma2(accA[2 * j],     xpA, wv.x);
        fma2(accB[2 * j],     xpB, wv.x);
        fma2(accA[2 * j + 1], xpA, wv.y);
        fma2(accB[2 * j + 1], xpB, wv.y);
      }
#pragma unroll
      for (int j = 0; j < JH; j++) {        // smem port (shared by both rows)
        ulonglong2 wv = sw[k * JH + j];
        fma2(accA[2 * (JC + j)],     xpA, wv.x);
        fma2(accB[2 * (JC + j)],     xpB, wv.x);
        fma2(accA[2 * (JC + j) + 1], xpA, wv.y);
        fma2(accB[2 * (JC + j) + 1], xpB, wv.y);
      }
    }
  }
#pragma unroll
  for (int j4 = 0; j4 < OD / 4; j4++) {
    uint32_t wA = quant_pack2(kt0, kt1, baseA + 4 * j4,     accA[2 * j4]);
    wA |= quant_pack2(kt0, kt1, baseA + 4 * j4 + 2, accA[2 * j4 + 1]) << 16;
    uint32_t wB = quant_pack2(kt0, kt1, baseB + 4 * j4,     accB[2 * j4]);
    wB |= quant_pack2(kt0, kt1, baseB + 4 * j4 + 2, accB[2 * j4 + 1]) << 16;
    hoA[j4] = wA;
    hoB[j4] = wB;
  }
}

__global__ void __launch_bounds__(TB, 5)
actor_l234(float* __restrict__ out, Keys K) {
  __shared__ ulonglong2 s_wB[160];     // L2 high @0 (96), L3 high @96 (48), L4 high @144 (16)
  __shared__ float s_tanh[257];
  int tid = threadIdx.x;
  {
    const ulonglong2* gw2 = (const ulonglong2*)g_nw;
#pragma unroll
    for (int i = 0; i < 2; i++) {
      int idx = tid + i * TB;
      if (idx < 160) {
        ulonglong2 v;
        if (idx < 96)       { int k = idx / 3, jh = idx % 3; v = gw2[512 + k * 6 + 3 + jh]; }
        else if (idx < 144) { int i2 = idx - 96; int k = i2 / 2, jh = i2 % 2; v = gw2[704 + k * 4 + 2 + jh]; }
        else                { int k = idx - 144; v = gw2[800 + k * 2 + 1]; }
        s_wB[idx] = v;
      }
    }
    for (int i = tid; i < 257; i += TB) s_tanh[i] = g_tanh[i];
  }
  __syncthreads();

  uint32_t rowA = blockIdx.x * (2 * TB) + tid;   // coalesced stream A
  uint32_t rowB = rowA + TB;                      // coalesced stream B

  uint32_t h1pA[8], h1pB[8];
  {
    uint4 a0 = g_h1[rowA * 2];
    uint4 a1 = g_h1[rowA * 2 + 1];
    uint4 b0 = g_h1[rowB * 2];
    uint4 b1 = g_h1[rowB * 2 + 1];
    h1pA[0] = a0.x; h1pA[1] = a0.y; h1pA[2] = a0.z; h1pA[3] = a0.w;
    h1pA[4] = a1.x; h1pA[5] = a1.y; h1pA[6] = a1.z; h1pA[7] = a1.w;
    h1pB[0] = b0.x; h1pB[1] = b0.y; h1pB[2] = b0.z; h1pB[3] = b0.w;
    h1pB[4] = b1.x; h1pB[5] = b1.y; h1pB[6] = b1.z; h1pB[7] = b1.w;
  }

  uint32_t h2pA[6], h2pB[6], h3pA[4], h3pB[4];
  dense_packed2<32, 24, 512, 3>(h1pA, h1pB, h2pA, h2pB, s_wB,
                                K.k[6],  K.k[7],  rowA * 24u, rowB * 24u);
  dense_packed2<24, 16, 704, 2>(h2pA, h2pB, h3pA, h3pB, s_wB + 96,
                                K.k[10], K.k[11], rowA * 16u, rowB * 16u);

  // ---- layer 4: j4=0 const, j4=1 smem (grouped); clip, tanh LUT ----
  {
    unsigned long long accA[4], accB[4];
#pragma unroll
    for (int j = 0; j < 4; j++) { accA[j] = 0ull; accB[j] = 0ull; }
#pragma unroll
    for (int k4 = 0; k4 < 4; k4++) {
      uint32_t pwA = h3pA[k4], pwB = h3pB[k4];
#pragma unroll
      for (int c = 0; c < 4; c++) {
        int k = 4 * k4 + c;
        uint32_t nA = (pwA >> (8 * c)) & 0xFFu;
        uint32_t nB = (pwB >> (8 * c)) & 0xFFu;
        float xsA = __fmul_rn((float)nA, C99_128);
        float xsB = __fmul_rn((float)nB, C99_128);
        unsigned long long xpA = pack2(xsA, xsA);
        unsigned long long xpB = pack2(xsB, xsB);
        {
          ulonglong2 wv = c_w[800 + k * 2];
          fma2(accA[0], xpA, wv.x);
          fma2(accB[0], xpB, wv.x);
          fma2(accA[1], xpA, wv.y);
          fma2(accB[1], xpB, wv.y);
        }
        {
          ulonglong2 wv = s_wB[144 + k];
          fma2(accA[2], xpA, wv.x);
          fma2(accB[2], xpB, wv.x);
          fma2(accA[3], xpA, wv.y);
          fma2(accB[3], xpB, wv.y);
        }
      }
    }
    uint32_t baseA = rowA * 8u, baseB = rowB * 8u;
    float o4A[8], o4B[8];
#pragma unroll
    for (int j = 0; j < 4; j++) {
      float a0, a1, b0, b1;
      unpack2(accA[j], a0, a1);
      unpack2(accB[j], b0, b1);
      float rA0 = quant_r(K.k[14], K.k[15], baseA + 2 * j,     a0);
      float rA1 = quant_r(K.k[14], K.k[15], baseA + 2 * j + 1, a1);
      float rB0 = quant_r(K.k[14], K.k[15], baseB + 2 * j,     b0);
      float rB1 = quant_r(K.k[14], K.k[15], baseB + 2 * j + 1, b1);
      rA0 = fminf(fmaxf(rA0, -128.0f), 128.0f);
      rA1 = fminf(fmaxf(rA1, -128.0f), 128.0f);
      rB0 = fminf(fmaxf(rB0, -128.0f), 128.0f);
      rB1 = fminf(fmaxf(rB1, -128.0f), 128.0f);
      o4A[2 * j]     = s_tanh[__float2int_rn(rA0) + 128];
      o4A[2 * j + 1] = s_tanh[__float2int_rn(rA1) + 128];
      o4B[2 * j]     = s_tanh[__float2int_rn(rB0) + 128];
      o4B[2 * j + 1] = s_tanh[__float2int_rn(rB1) + 128];
    }
    float* opA = out + (size_t)rowA * 8;
    float* opB = out + (size_t)rowB * 8;
    *(float4*)opA       = make_float4(o4A[0], o4A[1], o4A[2], o4A[3]);
    *(float4*)(opA + 4) = make_float4(o4A[4], o4A[5], o4A[6], o4A[7]);
    *(float4*)opB       = make_float4(o4B[0], o4B[1], o4B[2], o4B[3]);
    *(float4*)(opB + 4) = make_float4(o4B[4], o4B[5], o4B[6], o4B[7]);
  }
}

// ---------------------------------------------------------------------------
extern "C" void kernel_launch(void* const* d_in, const int* in_sizes, int n_in,
                              void* d_out, int out_size) {
  const float* x  = (const float*)d_in[0];
  const float* w1 = (const float*)d_in[1];
  const float* w2 = (const float*)d_in[2];
  const float* w3 = (const float*)d_in[3];
  const float* w4 = (const float*)d_in[4];
  int rows = in_sizes[0] / 64;

  Keys K;
  for (int i = 0; i < 8; i++) {
    uint32_t a, b;
    tf2x32(0u, 42u, 0u, (uint32_t)i, &a, &b);
    K.k[2 * i] = a; K.k[2 * i + 1] = b;
  }

  setup_weights<<<(3328 + 257 + 255) / 256, 256>>>(w1, w2, w3, w4, K);

  // Stage noisy weights into the constant bank (D2D, graph-capturable).
  void* src = nullptr;
  cudaGetSymbolAddress(&src, g_nw);
  cudaMemcpyToSymbolAsync(c_w, src, 3328 * sizeof(float), 0,
                          cudaMemcpyDeviceToDevice, 0);

  actor_l1<<<rows / TB, TB>>>(x, K);
  actor_l234<<<rows / (2 * TB), TB>>>((float*)d_out, K);
}

// round 16
// speedup vs baseline: 1.1136x; 1.0584x over previous
#include <cuda_runtime.h>
#include <stdint.h>

// ---------------------------------------------------------------------------
// JAX threefry2x32 (partitionable, verified R1). Lazy thermal noise (R3).
// R16: R12 EXACTLY (dual-port 1:1 const/smem split, two-kernel, 1 row/thread
// everywhere — the measured optimum across fusion/ratio/interleave/blocking),
// with ONE change: kernel A's occupancy cap 7 -> 8 blocks/SM (A's live state
// ~55 regs fits 64; +14% warps for latency hiding on the LDC/LDS chains).
// No arithmetic change -> bit-identical rel_err.
// ---------------------------------------------------------------------------
#define TB 128
#define ROWS_TOTAL 262144

struct Keys { unsigned int k[16]; };   // ks[i] = (k[2i], k[2i+1])

__device__ float g_nw[3328];           // noisy weights (k-major), staging
__device__ float g_tanh[257];          // tanh LUT on the 1/128 grid
__device__ uint4 g_h1[ROWS_TOTAL * 2]; // packed h1: 32B per row (8 MB)

// Const-bank copy of g_nw as 16B vectors (832 entries).
// L1: [0..512) k*8+j4; L2: [512..704) k*6+j4; L3: [704..800) k*4+j4;
// L4: [800..832) k*2+j4.
__constant__ ulonglong2 c_w[832];

__host__ __device__ __forceinline__ void tf2x32(uint32_t k0, uint32_t k1,
                                                uint32_t x0, uint32_t x1,
                                                uint32_t* o0, uint32_t* o1) {
  uint32_t ks2 = k0 ^ k1 ^ 0x1BD11BDAu;
#define TFR(a,b,r) { a += b; b = ((b << (r)) | (b >> (32 - (r)))); b ^= a; }
  x0 += k0; x1 += k1;
  TFR(x0,x1,13) TFR(x0,x1,15) TFR(x0,x1,26) TFR(x0,x1,6)
  x0 += k1;  x1 += ks2 + 1u;
  TFR(x0,x1,17) TFR(x0,x1,29) TFR(x0,x1,16) TFR(x0,x1,24)
  x0 += ks2; x1 += k0 + 2u;
  TFR(x0,x1,13) TFR(x0,x1,15) TFR(x0,x1,26) TFR(x0,x1,6)
  x0 += k0;  x1 += k1 + 3u;
  TFR(x0,x1,17) TFR(x0,x1,29) TFR(x0,x1,16) TFR(x0,x1,24)
  x0 += k1;  x1 += ks2 + 4u;
  TFR(x0,x1,13) TFR(x0,x1,15) TFR(x0,x1,26) TFR(x0,x1,6)
  x0 += ks2; x1 += k0 + 5u;
#undef TFR
  *o0 = x0; *o1 = x1;
}

// --- exact path (weight noise; ulps here shift every row) -------------------
__device__ __forceinline__ float erfinv_xla(float x) {
  float xx = __fmul_rn(x, x);
  float w  = -log1pf(-xx);
  float p;
  if (w < 5.0f) {
    w = __fadd_rn(w, -2.5f);
    p = 2.81022636e-08f;
    p = __fadd_rn(3.43273939e-07f,  __fmul_rn(p, w));
    p = __fadd_rn(-3.5233877e-06f,  __fmul_rn(p, w));
    p = __fadd_rn(-4.39150654e-06f, __fmul_rn(p, w));
    p = __fadd_rn(0.00021858087f,   __fmul_rn(p, w));
    p = __fadd_rn(-0.00125372503f,  __fmul_rn(p, w));
    p = __fadd_rn(-0.00417768164f,  __fmul_rn(p, w));
    p = __fadd_rn(0.246640727f,     __fmul_rn(p, w));
    p = __fadd_rn(1.50140941f,      __fmul_rn(p, w));
  } else {
    w = __fadd_rn(sqrtf(w), -3.0f);
    p = -0.000200214257f;
    p = __fadd_rn(0.000100950558f,  __fmul_rn(p, w));
    p = __fadd_rn(0.00134934322f,   __fmul_rn(p, w));
    p = __fadd_rn(-0.00367342844f,  __fmul_rn(p, w));
    p = __fadd_rn(0.00573950773f,   __fmul_rn(p, w));
    p = __fadd_rn(-0.0076224613f,   __fmul_rn(p, w));
    p = __fadd_rn(0.00943887047f,   __fmul_rn(p, w));
    p = __fadd_rn(1.00167406f,      __fmul_rn(p, w));
    p = __fadd_rn(2.83297682f,      __fmul_rn(p, w));
  }
  return __fmul_rn(p, x);
}

__device__ __forceinline__ float jax_normal_exact(uint32_t k0, uint32_t k1,
                                                  uint32_t idx) {
  uint32_t b0, b1;
  tf2x32(k0, k1, 0u, idx, &b0, &b1);
  uint32_t bits = b0 ^ b1;
  float f = __uint_as_float((bits >> 9) | 0x3f800000u);
  f = __fadd_rn(f, -1.0f);
  const float lo = -0x1.fffffep-1f;
  float u = __fadd_rn(__fmul_rn(f, 2.0f), lo);
  u = fmaxf(u, lo);
  return __fmul_rn(0x1.6a09e6p+0f, erfinv_xla(u));
}

// --- fast thermal path (rare): exact bits, ~1e-3 erfinv, sigma*sqrt2 folded -
#define SC(a) ((float)((a) * 1.1313708498984761e-06))

__device__ __noinline__ float add_thermal(uint32_t k0, uint32_t k1,
                                          uint32_t idx, float acc) {
  uint32_t b0, b1;
  tf2x32(k0, k1, 0u, idx, &b0, &b1);
  uint32_t bits = b0 ^ b1;
  float f = __uint_as_float((bits >> 9) | 0x3f800000u) - 1.0f;
  float u = fmaf(f, 2.0f, -0x1.fffffep-1f);
  float t = fmaf(u, -u, 1.0f);
  float w = fminf(-__logf(t), 5.0f);
  w = w - 2.5f;
  float p = SC(2.81022636e-08);
  p = fmaf(p, w, SC(3.43273939e-07));
  p = fmaf(p, w, SC(-3.5233877e-06));
  p = fmaf(p, w, SC(-4.39150654e-06));
  p = fmaf(p, w, SC(0.00021858087));
  p = fmaf(p, w, SC(-0.00125372503));
  p = fmaf(p, w, SC(-0.00417768164));
  p = fmaf(p, w, SC(0.246640727));
  p = fmaf(p, w, SC(1.50140941));
  return fmaf(p, u, acc);
}

__device__ __forceinline__ float quant_r(uint32_t kt0, uint32_t kt1,
                                         uint32_t idx, float acc) {
  float y = __fmul_rn(acc, 128.0f);
  float r = rintf(y);
  bool need = fabsf(__fadd_rn(y, -r)) >= 0.4985f;
  if (__builtin_expect((int)__ballot_sync(0xffffffffu, need), 0)) {
    float o = add_thermal(kt0, kt1, idx, acc);
    r = rintf(__fmul_rn(o, 128.0f));
  }
  return r;
}

// --- packed f32x2 helpers (sm_10x) ------------------------------------------
__device__ __forceinline__ unsigned long long pack2(float a, float b) {
  unsigned long long r;
  asm("mov.b64 %0, {%1, %2};" : "=l"(r) : "f"(a), "f"(b));
  return r;
}
__device__ __forceinline__ void unpack2(unsigned long long v, float& a, float& b) {
  asm("mov.b64 {%0, %1}, %2;" : "=f"(a), "=f"(b) : "l"(v));
}
__device__ __forceinline__ void fma2(unsigned long long& d,
                                     unsigned long long a, unsigned long long b) {
  asm("fma.rn.f32x2 %0, %1, %2, %0;" : "+l"(d) : "l"(a), "l"(b));
}
__device__ __forceinline__ unsigned long long mul2(unsigned long long a,
                                                   unsigned long long b) {
  unsigned long long r;
  asm("mul.rn.f32x2 %0, %1, %2;" : "=l"(r) : "l"(a), "l"(b));
  return r;
}
#define C99P 0x3F7D70A43F7D70A4ull  // (0.99f, 0.99f)
#define C99_128 (0.99f / 128.0f)    // exactly fl(0.99f)*2^-7

// ---------------------------------------------------------------------------
__global__ void setup_weights(const float* __restrict__ w1,
                              const float* __restrict__ w2,
                              const float* __restrict__ w3,
                              const float* __restrict__ w4, Keys K) {
  int e = blockIdx.x * blockDim.x + threadIdx.x;
  if (e >= 3328) {
    int te = e - 3328;
    if (te < 257) g_tanh[te] = tanhf((te - 128) * 0.0078125f);
    return;
  }
  int layer, off, ID, OD, li;
  const float* w;
  if (e < 2048)      { layer = 0; off = 0;    ID = 64; OD = 32; li = e;        w = w1; }
  else if (e < 2816) { layer = 1; off = 2048; ID = 32; OD = 24; li = e - 2048; w = w2; }
  else if (e < 3200) { layer = 2; off = 2816; ID = 24; OD = 16; li = e - 2816; w = w3; }
  else               { layer = 3; off = 3200; ID = 16; OD = 8;  li = e - 3200; w = w4; }
  int j = li / ID, kk = li % ID;
  float z = jax_normal_exact(K.k[4 * layer + 0], K.k[4 * layer + 1], (uint32_t)li);
  float g = expf(__fmul_rn(z, 0.12f));
  g_nw[off + kk * OD + j] = __fmul_rn(w[li], g);
}

// ---------------------------------------------------------------------------
// Epilogue for one accumulator pair: quantize+relu-clip, pack 2 bytes.
__device__ __forceinline__ uint32_t quant_pack2(uint32_t kt0, uint32_t kt1,
                                                uint32_t idx, unsigned long long acc) {
  float a, b;
  unpack2(acc, a, b);
  float r0 = quant_r(kt0, kt1, idx,     a);
  float r1 = quant_r(kt0, kt1, idx + 1, b);
  uint32_t n0 = (uint32_t)__float2int_rn(fminf(fmaxf(r0, 0.0f), 128.0f));
  uint32_t n1 = (uint32_t)__float2int_rn(fminf(fmaxf(r1, 0.0f), 128.0f));
  return n0 | (n1 << 8);
}

// ===========================================================================
// KERNEL A: layer 1. 1 row/thread. j4 0..3 const, 4..7 smem (R12), occ 8.
// ===========================================================================
__global__ void __launch_bounds__(TB, 8)
actor_l1(const float* __restrict__ x, Keys K) {
  __shared__ ulonglong2 s_w[256];      // [k][j4-4], 4 KB
  int tid = threadIdx.x;
  {
    const ulonglong2* gw2 = (const ulonglong2*)g_nw;
#pragma unroll
    for (int i = 0; i < 2; i++) {
      int idx = tid + i * TB;
      int k = idx >> 2, jh = idx & 3;
      s_w[idx] = gw2[k * 8 + 4 + jh];
    }
  }
  __syncthreads();

  uint32_t row = blockIdx.x * TB + tid;

  unsigned long long acc[16];
#pragma unroll
  for (int j = 0; j < 16; j++) acc[j] = 0ull;
  const float4* xr = (const float4*)(x + (size_t)row * 64);
#pragma unroll 4
  for (int k4 = 0; k4 < 16; k4++) {
    float4 xv = __ldg(xr + k4);
    float xk[4] = {xv.x, xv.y, xv.z, xv.w};
#pragma unroll
    for (int c = 0; c < 4; c++) {
      int k = 4 * k4 + c;
      unsigned long long xp = mul2(pack2(xk[c], xk[c]), C99P);
#pragma unroll
      for (int j = 0; j < 4; j++) {         // const port: outputs 0..15
        ulonglong2 wv = c_w[k * 8 + j];
        fma2(acc[2 * j],     xp, wv.x);
        fma2(acc[2 * j + 1], xp, wv.y);
      }
#pragma unroll
      for (int j = 0; j < 4; j++) {         // smem port: outputs 16..31
        ulonglong2 wv = s_w[k * 4 + j];
        fma2(acc[8 + 2 * j], xp, wv.x);
        fma2(acc[9 + 2 * j], xp, wv.y);
      }
    }
  }
  uint32_t base = row * 32u;
  uint32_t h1p[8];
#pragma unroll
  for (int j4 = 0; j4 < 8; j4++) {
    uint32_t w = quant_pack2(K.k[2], K.k[3], base + 4 * j4,     acc[2 * j4]);
    w |= quant_pack2(K.k[2], K.k[3], base + 4 * j4 + 2, acc[2 * j4 + 1]) << 16;
    h1p[j4] = w;
  }
  g_h1[row * 2]     = make_uint4(h1p[0], h1p[1], h1p[2], h1p[3]);
  g_h1[row * 2 + 1] = make_uint4(h1p[4], h1p[5], h1p[6], h1p[7]);
}

// ===========================================================================
// KERNEL B: layers 2-4, byte-packed, 1 row/thread (R12 exactly).
// ===========================================================================
template <int ID, int OD, int CBASE, int JC>
__device__ __forceinline__ void dense_packed(const uint32_t* __restrict__ hinP,
                                             uint32_t* __restrict__ houtP,
                                             const ulonglong2* __restrict__ sw,
                                             uint32_t kt0, uint32_t kt1,
                                             uint32_t base) {
  constexpr int JH = OD / 4 - JC;      // smem j4's per k
  unsigned long long acc[OD / 2];
#pragma unroll
  for (int j = 0; j < OD / 2; j++) acc[j] = 0ull;
#pragma unroll
  for (int k4 = 0; k4 < ID / 4; k4++) {
    uint32_t pw = hinP[k4];
#pragma unroll
    for (int c = 0; c < 4; c++) {
      int k = 4 * k4 + c;
      uint32_t n = (pw >> (8 * c)) & 0xFFu;
      float xs = __fmul_rn((float)n, C99_128);
      unsigned long long xp = pack2(xs, xs);
#pragma unroll
      for (int j = 0; j < JC; j++) {        // const port
        ulonglong2 wv = c_w[CBASE + k * (OD / 4) + j];
        fma2(acc[2 * j],     xp, wv.x);
        fma2(acc[2 * j + 1], xp, wv.y);
      }
#pragma unroll
      for (int j = 0; j < JH; j++) {        // smem port
        ulonglong2 wv = sw[k * JH + j];
        fma2(acc[2 * (JC + j)],     xp, wv.x);
        fma2(acc[2 * (JC + j) + 1], xp, wv.y);
      }
    }
  }
#pragma unroll
  for (int j4 = 0; j4 < OD / 4; j4++) {
    uint32_t w = quant_pack2(kt0, kt1, base + 4 * j4,     acc[2 * j4]);
    w |= quant_pack2(kt0, kt1, base + 4 * j4 + 2, acc[2 * j4 + 1]) << 16;
    houtP[j4] = w;
  }
}

__global__ void __launch_bounds__(TB, 8)
actor_l234(float* __restrict__ out, Keys K) {
  __shared__ ulonglong2 s_wB[160];     // L2 high @0 (96), L3 high @96 (48), L4 high @144 (16)
  __shared__ float s_tanh[257];
  int tid = threadIdx.x;
  {
    const ulonglong2* gw2 = (const ulonglong2*)g_nw;
#pragma unroll
    for (int i = 0; i < 2; i++) {
      int idx = tid + i * TB;
      if (idx < 160) {
        ulonglong2 v;
        if (idx < 96)       { int k = idx / 3, jh = idx % 3; v = gw2[512 + k * 6 + 3 + jh]; }
        else if (idx < 144) { int i2 = idx - 96; int k = i2 / 2, jh = i2 % 2; v = gw2[704 + k * 4 + 2 + jh]; }
        else                { int k = idx - 144; v = gw2[800 + k * 2 + 1]; }
        s_wB[idx] = v;
      }
    }
    for (int i = tid; i < 257; i += TB) s_tanh[i] = g_tanh[i];
  }
  __syncthreads();

  uint32_t row = blockIdx.x * TB + tid;

  uint32_t h1p[8];
  {
    uint4 a = g_h1[row * 2];
    uint4 b = g_h1[row * 2 + 1];
    h1p[0] = a.x; h1p[1] = a.y; h1p[2] = a.z; h1p[3] = a.w;
    h1p[4] = b.x; h1p[5] = b.y; h1p[6] = b.z; h1p[7] = b.w;
  }

  uint32_t h2p[6], h3p[4];
  dense_packed<32, 24, 512, 3>(h1p, h2p, s_wB,      K.k[6],  K.k[7],  row * 24u);
  dense_packed<24, 16, 704, 2>(h2p, h3p, s_wB + 96, K.k[10], K.k[11], row * 16u);

  // ---- layer 4: j4=0 const, j4=1 smem; no relu, clip, tanh LUT ----
  float o4[8];
  {
    unsigned long long acc[4];
#pragma unroll
    for (int j = 0; j < 4; j++) acc[j] = 0ull;
#pragma unroll
    for (int k4 = 0; k4 < 4; k4++) {
      uint32_t pw = h3p[k4];
#pragma unroll
      for (int c = 0; c < 4; c++) {
        int k = 4 * k4 + c;
        uint32_t n = (pw >> (8 * c)) & 0xFFu;
        float xs = __fmul_rn((float)n, C99_128);
        unsigned long long xp = pack2(xs, xs);
        {
          ulonglong2 wv = c_w[800 + k * 2];
          fma2(acc[0], xp, wv.x);
          fma2(acc[1], xp, wv.y);
        }
        {
          ulonglong2 wv = s_wB[144 + k];
          fma2(acc[2], xp, wv.x);
          fma2(acc[3], xp, wv.y);
        }
      }
    }
    uint32_t base = row * 8u;
#pragma unroll
    for (int j = 0; j < 4; j++) {
      float a, b;
      unpack2(acc[j], a, b);
      float r0 = quant_r(K.k[14], K.k[15], base + 2 * j,     a);
      float r1 = quant_r(K.k[14], K.k[15], base + 2 * j + 1, b);
      r0 = fminf(fmaxf(r0, -128.0f), 128.0f);
      r1 = fminf(fmaxf(r1, -128.0f), 128.0f);
      o4[2 * j]     = s_tanh[__float2int_rn(r0) + 128];
      o4[2 * j + 1] = s_tanh[__float2int_rn(r1) + 128];
    }
  }

  float* op = out + (size_t)row * 8;
  *(float4*)op       = make_float4(o4[0], o4[1], o4[2], o4[3]);
  *(float4*)(op + 4) = make_float4(o4[4], o4[5], o4[6], o4[7]);
}

// ---------------------------------------------------------------------------
extern "C" void kernel_launch(void* const* d_in, const int* in_sizes, int n_in,
                              void* d_out, int out_size) {
  const float* x  = (const float*)d_in[0];
  const float* w1 = (const float*)d_in[1];
  const float* w2 = (const float*)d_in[2];
  const float* w3 = (const float*)d_in[3];
  const float* w4 = (const float*)d_in[4];
  int rows = in_sizes[0] / 64;

  Keys K;
  for (int i = 0; i < 8; i++) {
    uint32_t a, b;
    tf2x32(0u, 42u, 0u, (uint32_t)i, &a, &b);
    K.k[2 * i] = a; K.k[2 * i + 1] = b;
  }

  setup_weights<<<(3328 + 257 + 255) / 256, 256>>>(w1, w2, w3, w4, K);

  // Stage noisy weights into the constant bank (D2D, graph-capturable).
  void* src = nullptr;
  cudaGetSymbolAddress(&src, g_nw);
  cudaMemcpyToSymbolAsync(c_w, src, 3328 * sizeof(float), 0,
                          cudaMemcpyDeviceToDevice, 0);

  actor_l1<<<rows / TB, TB>>>(x, K);
  actor_l234<<<rows / TB, TB>>>((float*)d_out, K);
}